// round 12
// baseline (speedup 1.0000x reference)
#include <cuda_runtime.h>
#include <cuda_fp16.h>

#define N_VN    24576
#define D_V     4
#define D_C     8
#define E_EDGES (N_VN * D_V)     // 98304
#define M_CN    (E_EDGES / D_C)  // 12288
#define BSZ     64
#define CLIPV   20.0f
#define EPSV    1e-12f
#define S15     3.0517578125e-05f   // 2^-15
#define S14     6.103515625e-05f    // 2^-14
#define LN2F    0.69314718056f

#define PLANEU2 (N_VN * 16)      // uint2 (=4 halves) elements per plane
#define BUFU2   (4 * PLANEU2)    // uint2 elements per buffer (4 slots)

// ---------------- scratch (device globals: allocation-free) ----------------
__device__ float g_llrT[N_VN * BSZ];               // llr transposed [vn][b]
__device__ uint2 g_c2v[2 * BUFU2];                 // double-buffered [buf][slot][vn][b/4]
__device__ int   g_vn_edges[N_VN * D_V];           // vn -> its 4 edges (sorted)
__device__ __align__(16) int g_eidx[E_EDGES];      // edge -> ro | (slot<<21)
__device__ int   g_vn_cnt[N_VN];

__device__ __forceinline__ float clipf(float v, float lo, float hi) {
    return fminf(fmaxf(v, lo), hi);
}
__device__ __forceinline__ __half2 h2(unsigned u) {
    return *reinterpret_cast<__half2*>(&u);
}
__device__ __forceinline__ float copysgn(float mag, float s) {
    return __int_as_float((__float_as_int(mag) & 0x7fffffff) |
                          (__float_as_int(s) & 0x80000000));
}

// ------------- setup: transpose llr + zero cnt + zero c2v buf0 -------------
__global__ void k_setup(const float* __restrict__ in) {
    __shared__ float tile[BSZ * 33];
    int n0 = blockIdx.x * 32;
    int t = threadIdx.x;
#pragma unroll
    for (int k = 0; k < 8; k++) {       // load 32n x 64b tile (b-major source)
        int idx = t + k * 256;
        int nn = idx & 31, b = idx >> 5;
        tile[b * 33 + nn] = in[b * N_VN + n0 + nn];
    }
    if (t < 32) g_vn_cnt[n0 + t] = 0;
    {   // zero buffer 0 of c2v: 1024 uint4 per block x 768 blocks
        uint4* c4 = reinterpret_cast<uint4*>(g_c2v);
        int base = blockIdx.x * 1024;
#pragma unroll
        for (int k = 0; k < 4; k++)
            c4[base + t + k * 256] = make_uint4(0u, 0u, 0u, 0u);
    }
    __syncthreads();
#pragma unroll
    for (int k = 0; k < 8; k++) {
        int idx = t + k * 256;
        int b = idx & 63, nn = idx >> 6;
        g_llrT[(n0 + nn) * BSZ + b] = tile[b * 33 + nn];
    }
}

__global__ void k_build_inverse(const int* __restrict__ e2v) {
    int e = blockIdx.x * blockDim.x + threadIdx.x;
    if (e < E_EDGES) {
        int n = e2v[e];
        int pos = atomicAdd(&g_vn_cnt[n], 1);
        g_vn_edges[n * D_V + pos] = e;
    }
}

// sort each VN's 4 edges ascending (deterministic slots); emit packed index
__global__ void k_sort4() {
    int n = blockIdx.x * blockDim.x + threadIdx.x;
    if (n >= N_VN) return;
    int* p = &g_vn_edges[n * 4];
    int a = p[0], b = p[1], c = p[2], d = p[3], x;
    if (a > b) { x = a; a = b; b = x; }
    if (c > d) { x = c; c = d; d = x; }
    if (a > c) { x = a; a = c; c = x; }
    if (b > d) { x = b; b = d; d = x; }
    if (b > c) { x = b; b = c; c = x; }
    p[0] = a; p[1] = b; p[2] = c; p[3] = d;
    int ro = n * 16;                    // ro < 2^19, slot in bits [21:23)
    g_eidx[a] = ro | (0 << 21);
    g_eidx[b] = ro | (1 << 21);
    g_eidx[c] = ro | (2 << 21);
    g_eidx[d] = ro | (3 << 21);
}

// ------------- fused per-iteration kernel: belief-on-the-fly CN ------------
// One thread = one CN x 4 batch lanes (16 threads per CN). Reads buffer rb,
// writes buffer rb^1 (double buffer). Division-free CN math:
//   a=(e^v-1)*2^-15, b=(e^v+1)*2^-15, B=prod b, C_j=prefA*sufA*b_j
//   u_j = (log2(B+C_j) - log2(B-C_j)) * ln2        (no divisions at all)
// launch_bounds(256,3): cap 84 regs -> 3 blocks/SM (occupancy over batching).
__global__ void __launch_bounds__(256, 3) k_cn(const float* __restrict__ cn_w,
                                               const float* __restrict__ ch_w,
                                               int it, int rb) {
    int idx = blockIdx.x * blockDim.x + threadIdx.x;   // M_CN * 16
    int cn = idx >> 4, qq = idx & 15;
    float cw  = __ldg(&cn_w[it]);
    float chw = __ldg(&ch_w[it]);
    const float oc = 0.999999f;
    // saturated value in log2 domain (reference's exact fp32 formula / ln2)
    float satl2 = __log2f(__fdividef(1.0f + oc, (1.0f - oc) + EPSV));
    float cwl2  = cw * LN2F;
    const uint2* rp = g_c2v + rb * BUFU2;
    uint2*       wp = g_c2v + (rb ^ 1) * BUFU2;
    const float4* llr4 = reinterpret_cast<const float4*>(g_llrT);

    // prefetch all 8 packed edge indices (2x LDG.128)
    const int4* ei4 = reinterpret_cast<const int4*>(g_eidx + cn * D_C);
    int4 eA = __ldg(ei4 + 0);
    int4 eB = __ldg(ei4 + 1);
    int pk[D_C] = {eA.x, eA.y, eA.z, eA.w, eB.x, eB.y, eB.z, eB.w};

    float4 a[D_C], s[D_C];
    int wfs[D_C];
    float4 B = make_float4(1.f, 1.f, 1.f, 1.f);
#pragma unroll
    for (int j = 0; j < D_C; j++) {
        int v = pk[j];
        int ro = (v & 0x1FFFFF) + qq;
        int wf = ro + (v >> 21) * PLANEU2;
        wfs[j] = wf;
        uint2 u0 = rp[ro];
        uint2 u1 = rp[ro + PLANEU2];
        uint2 u2 = rp[ro + 2 * PLANEU2];
        uint2 u3 = rp[ro + 3 * PLANEU2];
        uint2 uo = rp[wf];                         // own c2v (no slot selects)
        __half2 sA = __hadd2(__hadd2(h2(u0.x), h2(u1.x)), __hadd2(h2(u2.x), h2(u3.x)));
        __half2 sB = __hadd2(__hadd2(h2(u0.y), h2(u1.y)), __hadd2(h2(u2.y), h2(u3.y)));
        float2 sa = __half22float2(sA), sb = __half22float2(sB);
        float2 oa = __half22float2(h2(uo.x)), ob = __half22float2(h2(uo.y));
        float4 L = llr4[ro];
        float vx = clipf(fmaf(L.x, chw, sa.x) - oa.x, -CLIPV, CLIPV);
        float vy = clipf(fmaf(L.y, chw, sa.y) - oa.y, -CLIPV, CLIPV);
        float vz = clipf(fmaf(L.z, chw, sb.x) - ob.x, -CLIPV, CLIPV);
        float vw = clipf(fmaf(L.w, chw, sb.y) - ob.y, -CLIPV, CLIPV);
        float ex = __expf(vx), ey = __expf(vy), ez = __expf(vz), ew = __expf(vw);
        a[j].x = fmaf(ex, S15, -S15);
        a[j].y = fmaf(ey, S15, -S15);
        a[j].z = fmaf(ez, S15, -S15);
        a[j].w = fmaf(ew, S15, -S15);
        B.x *= fmaf(ex, S15, S15);
        B.y *= fmaf(ey, S15, S15);
        B.z *= fmaf(ez, S15, S15);
        B.w *= fmaf(ew, S15, S15);
    }

    // suffix products of a
    float4 S = make_float4(1.f, 1.f, 1.f, 1.f);
#pragma unroll
    for (int j = D_C - 1; j >= 0; j--) {
        s[j] = S;
        S.x *= a[j].x; S.y *= a[j].y; S.z *= a[j].z; S.w *= a[j].w;
    }

    // output pass: running prefix P, C = P*suf*b, u from two log2s
    float4 P = make_float4(1.f, 1.f, 1.f, 1.f);
#pragma unroll
    for (int j = 0; j < D_C; j++) {
        float bx = a[j].x + S14, by = a[j].y + S14;
        float bz = a[j].z + S14, bw = a[j].w + S14;
        float Cx = (P.x * s[j].x) * bx;
        float Cy = (P.y * s[j].y) * by;
        float Cz = (P.z * s[j].z) * bz;
        float Cw = (P.w * s[j].w) * bw;
        float dx = __log2f(B.x + Cx) - __log2f(B.x - Cx);
        float dy = __log2f(B.y + Cy) - __log2f(B.y - Cy);
        float dz = __log2f(B.z + Cz) - __log2f(B.z - Cz);
        float dw = __log2f(B.w + Cw) - __log2f(B.w - Cw);
        dx = (fabsf(Cx) > oc * B.x) ? copysgn(satl2, Cx) : dx;
        dy = (fabsf(Cy) > oc * B.y) ? copysgn(satl2, Cy) : dy;
        dz = (fabsf(Cz) > oc * B.z) ? copysgn(satl2, Cz) : dz;
        dw = (fabsf(Cw) > oc * B.w) ? copysgn(satl2, Cw) : dw;
        float cx = clipf(dx * cwl2, -CLIPV, CLIPV);
        float cy = clipf(dy * cwl2, -CLIPV, CLIPV);
        float cz = clipf(dz * cwl2, -CLIPV, CLIPV);
        float cwv = clipf(dw * cwl2, -CLIPV, CLIPV);
        __half2 ha = __floats2half2_rn(cx, cy);
        __half2 hb = __floats2half2_rn(cz, cwv);
        uint2 o;
        o.x = *reinterpret_cast<unsigned*>(&ha);
        o.y = *reinterpret_cast<unsigned*>(&hb);
        wp[wfs[j]] = o;
        P.x *= a[j].x; P.y *= a[j].y; P.z *= a[j].z; P.w *= a[j].w;
    }
}

// ---------------- final: dec = llr_in + sum c2v, transposed out ------------
__global__ void k_out(const float* __restrict__ in, float* __restrict__ out,
                      int fb) {
    __shared__ float tile[BSZ * 33];
    const __half* cv = reinterpret_cast<const __half*>(g_c2v + fb * BUFU2);
    int n0 = blockIdx.x * 32;
    int t = threadIdx.x;
#pragma unroll
    for (int k = 0; k < 8; k++) {       // b-fast mapping: coalesced plane reads
        int idx = t + k * 256;
        int b = idx & 63, nn = idx >> 6;
        int n = n0 + nn;
        float s = ((__half2float(cv[0 * N_VN * BSZ + n * BSZ + b]) +
                    __half2float(cv[1 * N_VN * BSZ + n * BSZ + b])) +
                    __half2float(cv[2 * N_VN * BSZ + n * BSZ + b])) +
                    __half2float(cv[3 * N_VN * BSZ + n * BSZ + b]);
        tile[b * 33 + nn] = s;
    }
    __syncthreads();
#pragma unroll
    for (int k = 0; k < 8; k++) {       // n-fast mapping: coalesced out writes
        int idx = t + k * 256;
        int nn = idx & 31, b = idx >> 5;
        out[b * N_VN + n0 + nn] = in[b * N_VN + n0 + nn] + tile[b * 33 + nn];
    }
}

// ---------------- launch ----------------
extern "C" void kernel_launch(void* const* d_in, const int* in_sizes, int n_in,
                              void* d_out, int out_size) {
    const float* llr  = (const float*)d_in[0];
    const float* cn_w = (const float*)d_in[1];
    const float* ch_w = (const float*)d_in[2];
    const int*   e2v  = (const int*)d_in[3];
    int iters = in_sizes[1];   // cn_weight length

    k_setup<<<N_VN / 32, 256>>>(llr);
    k_build_inverse<<<(E_EDGES + 255) / 256, 256>>>(e2v);
    k_sort4<<<(N_VN + 255) / 256, 256>>>();

    for (int it = 0; it < iters; it++)
        k_cn<<<(M_CN * 16) / 256, 256>>>(cn_w, ch_w, it, it & 1);

    k_out<<<N_VN / 32, 256>>>(llr, (float*)d_out, iters & 1);
}